// round 8
// baseline (speedup 1.0000x reference)
#include <cuda_runtime.h>

#define BB 512
#define SS 1024
#define TT 64
#define NB 2                     // batches per warp (interleaved chains)
#define WARPS_PER_CTA 2
#define CTAS (BB / (WARPS_PER_CTA * NB))   // 128

// Precomputed shifted transition exponentials (step-invariant).
__device__ float g_E[TT * TT];     // E'[t][k] = exp(trans[t][k] - rowmax[t])
__device__ float g_rmax[TT];       // rowmax[t] = max_k trans[t][k]

// ---------------------------------------------------------------------------
// prep: E' = exp(trans - rowmax) ; one block per row t, 64 threads (2 warps)
// ---------------------------------------------------------------------------
__global__ void crf_prep_kernel(const float* __restrict__ trans) {
    int t = blockIdx.x;
    int k = threadIdx.x;
    float x = trans[t * TT + k];

    __shared__ float sm[2];
    int i = __float_as_int(x);
    i = (i >= 0) ? i : (i ^ 0x7FFFFFFF);
    i = __reduce_max_sync(0xFFFFFFFFu, i);
    float wm = __int_as_float((i >= 0) ? i : (i ^ 0x7FFFFFFF));
    if ((k & 31) == 0) sm[k >> 5] = wm;
    __syncthreads();
    float rmax = fmaxf(sm[0], sm[1]);

    g_E[t * TT + k] = __expf(x - rmax);
    if (k == 0) g_rmax[t] = rmax;
}

// ---------------------------------------------------------------------------
// packed f32x2 helpers (Blackwell packed fp32 pipe; PTX-only)
// ---------------------------------------------------------------------------
typedef unsigned long long u64;

__device__ __forceinline__ u64 pk2(float lo, float hi) {
    u64 r; asm("mov.b64 %0, {%1, %2};" : "=l"(r) : "f"(lo), "f"(hi)); return r;
}
__device__ __forceinline__ void upk2(float& lo, float& hi, u64 v) {
    asm("mov.b64 {%0, %1}, %2;" : "=f"(lo), "=f"(hi) : "l"(v));
}
__device__ __forceinline__ u64 fma2(u64 a, u64 b, u64 c) {
    u64 d; asm("fma.rn.f32x2 %0, %1, %2, %3;" : "=l"(d) : "l"(a), "l"(b), "l"(c));
    return d;
}
__device__ __forceinline__ u64 add2(u64 a, u64 b) {
    u64 d; asm("add.rn.f32x2 %0, %1, %2;" : "=l"(d) : "l"(a), "l"(b));
    return d;
}

// warp-wide float max via monotone int mapping + single REDUX
__device__ __forceinline__ float warp_fmax(float x) {
    int i = __float_as_int(x);
    i = (i >= 0) ? i : (i ^ 0x7FFFFFFF);
    i = __reduce_max_sync(0xFFFFFFFFu, i);
    return __int_as_float((i >= 0) ? i : (i ^ 0x7FFFFFFF));
}

// ---------------------------------------------------------------------------
// main scan: one warp handles NB batches (interleaved independent chains);
// lane owns states (lane, lane+32)
// ---------------------------------------------------------------------------
__global__ void __launch_bounds__(WARPS_PER_CTA * 32, 1) crf_scan_kernel(
    const float* __restrict__ feats,   // [B, S, T]
    const float* __restrict__ masks,   // [B, S]
    float* __restrict__ out)           // [B, T]
{
    const int wid  = threadIdx.x >> 5;
    const int lane = threadIdx.x & 31;
    const int bbase = (blockIdx.x * WARPS_PER_CTA + wid) * NB;
    const int t0 = lane, t1 = lane + 32;

    // per-warp, per-batch double-buffered v exchange (broadcast -> conflict-free)
    __shared__ __align__(16) float vbuf[WARPS_PER_CTA][NB][2][TT];

    // E' rows for this lane's two states, packed as f32x2 pairs (128 regs,
    // SHARED across the NB batch chains)
    u64 e0[32], e1[32];
    {
        const float4* r0p = (const float4*)(g_E + t0 * TT);
        const float4* r1p = (const float4*)(g_E + t1 * TT);
#pragma unroll
        for (int j = 0; j < 16; j++) {
            float4 a = r0p[j];
            e0[2 * j]     = pk2(a.x, a.y);
            e0[2 * j + 1] = pk2(a.z, a.w);
            float4 c = r1p[j];
            e1[2 * j]     = pk2(c.x, c.y);
            e1[2 * j + 1] = pk2(c.z, c.w);
        }
    }
    const float r0 = g_rmax[t0];
    const float r1 = g_rmax[t1];

    const float* fptr[NB];
    const float* mptr[NB];
    float a0[NB], a1[NB];
    float fA0[NB], fA1[NB], mA[NB];
    float fB0[NB], fB1[NB], mB[NB];

#pragma unroll
    for (int u = 0; u < NB; u++) {
        fptr[u] = feats + (long)(bbase + u) * SS * TT;
        mptr[u] = masks + (long)(bbase + u) * SS;
        a0[u] = fptr[u][t0];
        a1[u] = fptr[u][t1];
        // distance-2 prefetch pipeline
        fA0[u] = __ldg(fptr[u] + TT + t0);
        fA1[u] = __ldg(fptr[u] + TT + t1);
        mA[u]  = __ldg(mptr[u] + 1);
        fB0[u] = __ldg(fptr[u] + 2 * TT + t0);
        fB1[u] = __ldg(fptr[u] + 2 * TT + t1);
        mB[u]  = __ldg(mptr[u] + 2);
    }

    int p = 0;
    for (int i = 1; i < SS; i++) {
        // issue prefetch for step i+2 (off the dependent chains)
        float fC0[NB], fC1[NB], mC[NB];
#pragma unroll
        for (int u = 0; u < NB; u++) { fC0[u] = 0.f; fC1[u] = 0.f; mC[u] = 0.f; }
        if (i + 2 < SS) {
#pragma unroll
            for (int u = 0; u < NB; u++) {
                const float* fp = fptr[u] + (i + 2) * TT;
                fC0[u] = __ldg(fp + t0);
                fC1[u] = __ldg(fp + t1);
                mC[u]  = __ldg(mptr[u] + i + 2);
            }
        }

        // m = max_k alpha[k] per batch (independent REDUXes pipeline)
        float m[NB];
#pragma unroll
        for (int u = 0; u < NB; u++)
            m[u] = warp_fmax(fmaxf(a0[u], a1[u]));

        // v = exp(alpha - m); publish both batches, then one syncwarp
#pragma unroll
        for (int u = 0; u < NB; u++) {
            float* vb = vbuf[wid][u][p];
            vb[t0] = __expf(a0[u] - m[u]);
            vb[t1] = __expf(a1[u] - m[u]);
        }
        __syncwarp();

        // dot: sum_k v[k] * E'[t][k]; NB independent accumulator sets
        float sum0[NB], sum1[NB];
#pragma unroll
        for (int u = 0; u < NB; u++) {
            const ulonglong2* vv = (const ulonglong2*)vbuf[wid][u][p];
            u64 A0 = pk2(0.f, 0.f), A1 = A0, B0 = A0, B1 = A0;
#pragma unroll
            for (int j = 0; j < 16; j++) {
                ulonglong2 q = vv[j];
                A0 = fma2(q.x, e0[2 * j],     A0);
                A1 = fma2(q.y, e0[2 * j + 1], A1);
                B0 = fma2(q.x, e1[2 * j],     B0);
                B1 = fma2(q.y, e1[2 * j + 1], B1);
            }
            float s0lo, s0hi, s1lo, s1hi;
            upk2(s0lo, s0hi, add2(A0, A1));
            upk2(s1lo, s1hi, add2(B0, B1));
            sum0[u] = s0lo + s0hi;
            sum1[u] = s1lo + s1hi;
        }

        // new alpha = feat + m + rowmax + log(sum) ; mask blend as in reference
#pragma unroll
        for (int u = 0; u < NB; u++) {
            float n0 = fA0[u] + m[u] + r0 + __logf(sum0[u]);
            float n1 = fA1[u] + m[u] + r1 + __logf(sum1[u]);
            a0[u] = n0 * mA[u] + a0[u] * (1.0f - mA[u]);
            a1[u] = n1 * mA[u] + a1[u] * (1.0f - mA[u]);

            // rotate prefetch registers
            fA0[u] = fB0[u]; fA1[u] = fB1[u]; mA[u] = mB[u];
            fB0[u] = fC0[u]; fB1[u] = fC1[u]; mB[u] = mC[u];
        }
        p ^= 1;
    }

#pragma unroll
    for (int u = 0; u < NB; u++) {
        out[(bbase + u) * TT + t0] = a0[u];
        out[(bbase + u) * TT + t1] = a1[u];
    }
}

// ---------------------------------------------------------------------------
// launch
// ---------------------------------------------------------------------------
extern "C" void kernel_launch(void* const* d_in, const int* in_sizes, int n_in,
                              void* d_out, int out_size) {
    const float* feats = (const float*)d_in[0];  // [512, 1024, 64]
    const float* masks = (const float*)d_in[1];  // [512, 1024]
    const float* trans = (const float*)d_in[2];  // [64, 64]
    float* out = (float*)d_out;                  // [512, 64]

    crf_prep_kernel<<<TT, TT>>>(trans);
    crf_scan_kernel<<<CTAS, WARPS_PER_CTA * 32>>>(feats, masks, out);
}

// round 9
// speedup vs baseline: 1.9066x; 1.9066x over previous
#include <cuda_runtime.h>

#define BB 512
#define SS 1024
#define TT 64
#define WARPS_PER_CTA 4
#define CTAS (BB / WARPS_PER_CTA)   // 128

#define LOG2E 1.4426950408889634f
#define LN2   0.6931471805599453f
#define LN64  4.1588830833596715f

// Precomputed shifted transition exponentials (step-invariant).
__device__ float g_E[TT * TT];     // E'[t][k] = exp(trans[t][k] - rowmax[t])
__device__ float g_rmax[TT];       // rowmax[t] = max_k trans[t][k]

// ---------------------------------------------------------------------------
// prep: E' = exp(trans - rowmax) ; one block per row t, 64 threads (2 warps)
// ---------------------------------------------------------------------------
__global__ void crf_prep_kernel(const float* __restrict__ trans) {
    int t = blockIdx.x;
    int k = threadIdx.x;
    float x = trans[t * TT + k];

    __shared__ float sm[2];
    int i = __float_as_int(x);
    i = (i >= 0) ? i : (i ^ 0x7FFFFFFF);
    i = __reduce_max_sync(0xFFFFFFFFu, i);
    float wm = __int_as_float((i >= 0) ? i : (i ^ 0x7FFFFFFF));
    if ((k & 31) == 0) sm[k >> 5] = wm;
    __syncthreads();
    float rmax = fmaxf(sm[0], sm[1]);

    g_E[t * TT + k] = __expf(x - rmax);
    if (k == 0) g_rmax[t] = rmax;
}

// ---------------------------------------------------------------------------
// packed f32x2 helpers (Blackwell packed fp32 pipe; PTX-only)
// ---------------------------------------------------------------------------
typedef unsigned long long u64;

__device__ __forceinline__ u64 pk2(float lo, float hi) {
    u64 r; asm("mov.b64 %0, {%1, %2};" : "=l"(r) : "f"(lo), "f"(hi)); return r;
}
__device__ __forceinline__ void upk2(float& lo, float& hi, u64 v) {
    asm("mov.b64 {%0, %1}, %2;" : "=f"(lo), "=f"(hi) : "l"(v));
}
__device__ __forceinline__ u64 fma2(u64 a, u64 b, u64 c) {
    u64 d; asm("fma.rn.f32x2 %0, %1, %2, %3;" : "=l"(d) : "l"(a), "l"(b), "l"(c));
    return d;
}
__device__ __forceinline__ u64 add2(u64 a, u64 b) {
    u64 d; asm("add.rn.f32x2 %0, %1, %2;" : "=l"(d) : "l"(a), "l"(b));
    return d;
}
__device__ __forceinline__ float ex2(float x) {
    float r; asm("ex2.approx.ftz.f32 %0, %1;" : "=f"(r) : "f"(x)); return r;
}
__device__ __forceinline__ float lg2(float x) {
    float r; asm("lg2.approx.ftz.f32 %0, %1;" : "=f"(r) : "f"(x)); return r;
}

// monotone float<->ordered-int map for REDUX-based float max
__device__ __forceinline__ int fmap(float x) {
    int i = __float_as_int(x);
    return (i >= 0) ? i : (i ^ 0x7FFFFFFF);
}
__device__ __forceinline__ float funmap(int i) {
    return __int_as_float((i >= 0) ? i : (i ^ 0x7FFFFFFF));
}

// ---------------------------------------------------------------------------
// main scan: one warp per batch; lane owns states (lane, lane+32).
// Log2-domain recurrence; shift s is a rigorous upper bound anchored to the
// exact warp-max two steps back (REDUX fully off the critical chain).
// ---------------------------------------------------------------------------
__global__ void __launch_bounds__(WARPS_PER_CTA * 32, 1) crf_scan_kernel(
    const float* __restrict__ feats,   // [B, S, T]
    const float* __restrict__ masks,   // [B, S]
    float* __restrict__ out)           // [B, T]
{
    const int wid  = threadIdx.x >> 5;
    const int lane = threadIdx.x & 31;
    const int b    = blockIdx.x * WARPS_PER_CTA + wid;
    const int t0 = lane, t1 = lane + 32;

    // per-warp double-buffered v exchange (broadcast reads -> conflict-free)
    __shared__ __align__(16) float vbuf[WARPS_PER_CTA][2][TT];

    // E' rows for this lane's two states, packed as f32x2 pairs (128 regs)
    u64 e0[32], e1[32];
    {
        const float4* r0p = (const float4*)(g_E + t0 * TT);
        const float4* r1p = (const float4*)(g_E + t1 * TT);
#pragma unroll
        for (int j = 0; j < 16; j++) {
            float4 a = r0p[j];
            e0[2 * j]     = pk2(a.x, a.y);
            e0[2 * j + 1] = pk2(a.z, a.w);
            float4 c = r1p[j];
            e1[2 * j]     = pk2(c.x, c.y);
            e1[2 * j + 1] = pk2(c.z, c.w);
        }
    }
    const float rm0 = g_rmax[t0];
    const float rm1 = g_rmax[t1];
    const float r20 = rm0 * LOG2E;   // row shift in log2 domain
    const float r21 = rm1 * LOG2E;

    // Rp2 = (max_{t,k} trans + ln 64) * log2e  -- per-step growth bound const.
    // max trans = max_t rmax[t], computed warp-wide from rmax registers.
    const float maxT = funmap(__reduce_max_sync(0xFFFFFFFFu,
                              fmap(fmaxf(rm0, rm1))));
    const float Rp2 = (maxT + LN64) * LOG2E;

    const float* fptr = feats + (long)b * SS * TT;
    const float* mptr = masks + (long)b * SS;

    // alpha0 = feats[:, 0, :]  (log2 domain)
    float a0 = fptr[t0] * LOG2E;
    float a1 = fptr[t1] * LOG2E;

    // distance-2 feats/mask prefetch pipeline (raw feats; log2e folded later)
    float fA0 = __ldg(fptr + TT + t0),     fA1 = __ldg(fptr + TT + t1);
    float mA  = __ldg(mptr + 1);
    float fB0 = __ldg(fptr + 2 * TT + t0), fB1 = __ldg(fptr + 2 * TT + t1);
    float mB  = __ldg(mptr + 2);

    // pending REDUX of current alpha (exact max anchor, consumed next step)
    int redA = __reduce_max_sync(0xFFFFFFFFu, fmap(fmaxf(a0, a1)));
    float sC = funmap(redA);   // shift for step 1: exact max of a_0

    int p = 0;
    for (int i = 1; i < SS; i++) {
        // ---- off-chain work: prefetch i+2, shift maintenance -------------
        float fC0 = 0.f, fC1 = 0.f, mC = 0.f;
        if (i + 2 < SS) {
            const float* fp = fptr + (i + 2) * TT;
            fC0 = __ldg(fp + t0);
            fC1 = __ldg(fp + t1);
            mC  = __ldg(mptr + i + 2);
        }
        // exact max of a_{i-1} (REDUX issued at end of prev step)
        float m2prev = funmap(redA);
        // max feat at this step (fA = feat_i), off-chain REDUX
        int redF = __reduce_max_sync(0xFFFFFFFFu, fmap(fmaxf(fA0, fA1)));
        float mf = funmap(redF);
        // shift for NEXT step: s_{i+1} = m_{i-1} + max(0, mf*log2e + Rp2)
        float sN = m2prev + fmaxf(0.0f, fmaf(mf, LOG2E, Rp2));
        // precombine n-tail constants: F = feat*log2e + s_i + r2
        float F0 = fmaf(fA0, LOG2E, sC + r20);
        float F1 = fmaf(fA1, LOG2E, sC + r21);

        // ---- critical chain ---------------------------------------------
        // v = 2^(a - s)
        float v0 = ex2(a0 - sC);
        float v1 = ex2(a1 - sC);
        float* vb = vbuf[wid][p];
        vb[t0] = v0;
        vb[t1] = v1;
        __syncwarp();

        // dot: sum_k v[k] * E'[t][k], packed pairs, 4 independent chains
        const ulonglong2* vv = (const ulonglong2*)vb;
        u64 A0 = pk2(0.f, 0.f), A1 = A0, B0 = A0, B1 = A0;
#pragma unroll
        for (int j = 0; j < 16; j++) {
            ulonglong2 q = vv[j];
            A0 = fma2(q.x, e0[2 * j],     A0);
            A1 = fma2(q.y, e0[2 * j + 1], A1);
            B0 = fma2(q.x, e1[2 * j],     B0);
            B1 = fma2(q.y, e1[2 * j + 1], B1);
        }
        float s0lo, s0hi, s1lo, s1hi;
        upk2(s0lo, s0hi, add2(A0, A1));
        upk2(s1lo, s1hi, add2(B0, B1));

        // new alpha (log2 domain) = F + log2(sum); mask blend a += m*(n-a)
        float n0 = F0 + lg2(s0lo + s0hi);
        float n1 = F1 + lg2(s1lo + s1hi);
        a0 = fmaf(mA, n0 - a0, a0);
        a1 = fmaf(mA, n1 - a1, a1);

        // issue exact-max REDUX of a_i (consumed at step i+1, off-chain)
        redA = __reduce_max_sync(0xFFFFFFFFu, fmap(fmaxf(a0, a1)));

        // rotate shift + prefetch registers
        sC = sN;
        fA0 = fB0; fA1 = fB1; mA = mB;
        fB0 = fC0; fB1 = fC1; mB = mC;
        p ^= 1;
    }

    // back to natural log
    out[b * TT + t0] = a0 * LN2;
    out[b * TT + t1] = a1 * LN2;
}

// ---------------------------------------------------------------------------
// launch
// ---------------------------------------------------------------------------
extern "C" void kernel_launch(void* const* d_in, const int* in_sizes, int n_in,
                              void* d_out, int out_size) {
    const float* feats = (const float*)d_in[0];  // [512, 1024, 64]
    const float* masks = (const float*)d_in[1];  // [512, 1024]
    const float* trans = (const float*)d_in[2];  // [64, 64]
    float* out = (float*)d_out;                  // [512, 64]

    crf_prep_kernel<<<TT, TT>>>(trans);
    crf_scan_kernel<<<CTAS, WARPS_PER_CTA * 32>>>(feats, masks, out);
}

// round 10
// speedup vs baseline: 2.0939x; 1.0982x over previous
#include <cuda_runtime.h>

#define BB 512
#define SS 1024
#define TT 64
#define WARPS_PER_CTA 4
#define CTAS (BB / WARPS_PER_CTA)   // 128

#define LOG2E 1.4426950408889634f
#define LN2   0.6931471805599453f
#define LN64  4.1588830833596715f

// Precomputed shifted transition exponentials (step-invariant).
__device__ float g_E[TT * TT];     // E'[t][k] = exp(trans[t][k] - rowmax[t])
__device__ float g_rmax[TT];       // rowmax[t] = max_k trans[t][k]

// ---------------------------------------------------------------------------
// prep: E' = exp(trans - rowmax) ; one block per row t, 64 threads (2 warps)
// ---------------------------------------------------------------------------
__global__ void crf_prep_kernel(const float* __restrict__ trans) {
    int t = blockIdx.x;
    int k = threadIdx.x;
    float x = trans[t * TT + k];

    __shared__ float sm[2];
    int i = __float_as_int(x);
    i = (i >= 0) ? i : (i ^ 0x7FFFFFFF);
    i = __reduce_max_sync(0xFFFFFFFFu, i);
    float wm = __int_as_float((i >= 0) ? i : (i ^ 0x7FFFFFFF));
    if ((k & 31) == 0) sm[k >> 5] = wm;
    __syncthreads();
    float rmax = fmaxf(sm[0], sm[1]);

    g_E[t * TT + k] = __expf(x - rmax);
    if (k == 0) g_rmax[t] = rmax;
}

// ---------------------------------------------------------------------------
// packed f32x2 helpers (Blackwell packed fp32 pipe; PTX-only)
// ---------------------------------------------------------------------------
typedef unsigned long long u64;

__device__ __forceinline__ u64 pk2(float lo, float hi) {
    u64 r; asm("mov.b64 %0, {%1, %2};" : "=l"(r) : "f"(lo), "f"(hi)); return r;
}
__device__ __forceinline__ void upk2(float& lo, float& hi, u64 v) {
    asm("mov.b64 {%0, %1}, %2;" : "=f"(lo), "=f"(hi) : "l"(v));
}
__device__ __forceinline__ u64 fma2(u64 a, u64 b, u64 c) {
    u64 d; asm("fma.rn.f32x2 %0, %1, %2, %3;" : "=l"(d) : "l"(a), "l"(b), "l"(c));
    return d;
}
__device__ __forceinline__ u64 add2(u64 a, u64 b) {
    u64 d; asm("add.rn.f32x2 %0, %1, %2;" : "=l"(d) : "l"(a), "l"(b));
    return d;
}
__device__ __forceinline__ float ex2(float x) {
    float r; asm("ex2.approx.ftz.f32 %0, %1;" : "=f"(r) : "f"(x)); return r;
}
__device__ __forceinline__ float lg2(float x) {
    float r; asm("lg2.approx.ftz.f32 %0, %1;" : "=f"(r) : "f"(x)); return r;
}

// monotone float<->ordered-int map for REDUX-based float max (general floats)
__device__ __forceinline__ int fmap(float x) {
    int i = __float_as_int(x);
    return (i >= 0) ? i : (i ^ 0x7FFFFFFF);
}
__device__ __forceinline__ float funmap(int i) {
    return __int_as_float((i >= 0) ? i : (i ^ 0x7FFFFFFF));
}

// ---------------------------------------------------------------------------
// main scan: one warp per batch; lane owns states (lane, lane+32).
//
// Exp-domain chain: the recurrence carries P[t] = 2^(A[t] - s) directly.
//   P_next = S * G,  S = dot(E'[t,:], P),  G = 2^(F - s')   (G off-chain)
// so NO MUFU op sits on the serial chain. Log-domain A is maintained
// off-chain (needed for the output, incl. underflowed states, and for
// binary-mask blending). Shift s' is a rigorous upper bound anchored at the
// exact warp max of the previous alpha (REDUX on positive P, off-chain).
// ---------------------------------------------------------------------------
__global__ void __launch_bounds__(WARPS_PER_CTA * 32, 1) crf_scan_kernel(
    const float* __restrict__ feats,   // [B, S, T]
    const float* __restrict__ masks,   // [B, S]
    float* __restrict__ out)           // [B, T]
{
    const int wid  = threadIdx.x >> 5;
    const int lane = threadIdx.x & 31;
    const int b    = blockIdx.x * WARPS_PER_CTA + wid;
    const int t0 = lane, t1 = lane + 32;

    // per-warp double-buffered P exchange (broadcast reads -> conflict-free)
    __shared__ __align__(16) float vbuf[WARPS_PER_CTA][2][TT];

    // E' rows for this lane's two states, packed as f32x2 pairs (128 regs)
    u64 e0[32], e1[32];
    {
        const float4* r0p = (const float4*)(g_E + t0 * TT);
        const float4* r1p = (const float4*)(g_E + t1 * TT);
#pragma unroll
        for (int j = 0; j < 16; j++) {
            float4 a = r0p[j];
            e0[2 * j]     = pk2(a.x, a.y);
            e0[2 * j + 1] = pk2(a.z, a.w);
            float4 c = r1p[j];
            e1[2 * j]     = pk2(c.x, c.y);
            e1[2 * j + 1] = pk2(c.z, c.w);
        }
    }
    const float rm0 = g_rmax[t0];
    const float rm1 = g_rmax[t1];
    const float r20 = rm0 * LOG2E;   // row shift in log2 domain
    const float r21 = rm1 * LOG2E;

    // Rp2 = (max_{t,k} trans + ln 64) * log2e  -- per-step growth bound const.
    const float maxT = funmap(__reduce_max_sync(0xFFFFFFFFu,
                              fmap(fmaxf(rm0, rm1))));
    const float Rp2 = (maxT + LN64) * LOG2E;

    const float* fptr = feats + (long)b * SS * TT;
    const float* mptr = masks + (long)b * SS;

    // alpha0 = feats[:, 0, :]  (log2 domain, off-chain shadow)
    float A0 = fptr[t0] * LOG2E;
    float A1 = fptr[t1] * LOG2E;

    // distance-2 feats/mask prefetch pipeline (raw feats)
    float fA0 = __ldg(fptr + TT + t0),     fA1 = __ldg(fptr + TT + t1);
    float mA  = __ldg(mptr + 1);
    float fB0 = __ldg(fptr + 2 * TT + t0), fB1 = __ldg(fptr + 2 * TT + t1);
    float mB  = __ldg(mptr + 2);

    // s_1 = exact max of A_0 ; P = 2^(A_0 - s_1)
    float sC = funmap(__reduce_max_sync(0xFFFFFFFFu, fmap(fmaxf(A0, A1))));
    float P0 = ex2(A0 - sC);
    float P1 = ex2(A1 - sC);
    // REDUX over positive P: int compare == float compare for x >= 0
    int redP = __reduce_max_sync(0xFFFFFFFFu, __float_as_int(fmaxf(P0, P1)));

    int p = 0;
#pragma unroll 2
    for (int i = 1; i < SS; i++) {
        // ---- critical chain head: publish P immediately ------------------
        float* vb = vbuf[wid][p];
        vb[t0] = P0;
        vb[t1] = P1;
        __syncwarp();

        // ---- off-chain: prefetch i+2 (branch-free, clamped) --------------
        const int ip2 = (i + 2 < SS) ? (i + 2) : (SS - 1);
        const float* fp = fptr + ip2 * TT;
        float fC0 = __ldg(fp + t0);
        float fC1 = __ldg(fp + t1);
        float mC  = __ldg(mptr + ip2);

        // ---- off-chain: shift maintenance --------------------------------
        // maxA_{i-1} = s_i + log2(max P_i)   (redP from previous step)
        float maxA = sC + lg2(__int_as_float(redP));
        // max feat_i off-chain
        float mf = funmap(__reduce_max_sync(0xFFFFFFFFu,
                          fmap(fmaxf(fA0, fA1))));
        // s_{i+1} = maxA_{i-1} + max(0, mf*log2e + Rp2)
        float sN = maxA + fmaxf(0.0f, fmaf(mf, LOG2E, Rp2));
        // F = feat*log2e + s_i + r2 ; G = 2^(F - s_{i+1}) ; H = 2^(s_i - s_{i+1})
        float F0 = fmaf(fA0, LOG2E, sC + r20);
        float F1 = fmaf(fA1, LOG2E, sC + r21);
        float G0 = ex2(F0 - sN);
        float G1 = ex2(F1 - sN);
        float H  = ex2(sC - sN);

        // ---- critical chain: dot sum_k P[k] * E'[t][k] -------------------
        const ulonglong2* vv = (const ulonglong2*)vb;
        u64 Aa0 = pk2(0.f, 0.f), Aa1 = Aa0, Bb0 = Aa0, Bb1 = Aa0;
#pragma unroll
        for (int j = 0; j < 16; j++) {
            ulonglong2 q = vv[j];
            Aa0 = fma2(q.x, e0[2 * j],     Aa0);
            Aa1 = fma2(q.y, e0[2 * j + 1], Aa1);
            Bb0 = fma2(q.x, e1[2 * j],     Bb0);
            Bb1 = fma2(q.y, e1[2 * j + 1], Bb1);
        }
        float s0lo, s0hi, s1lo, s1hi;
        upk2(s0lo, s0hi, add2(Aa0, Aa1));
        upk2(s1lo, s1hi, add2(Bb0, Bb1));
        float S0 = s0lo + s0hi;
        float S1 = s1lo + s1hi;

        // ---- chain tail: next P (1 FMUL + select; no MUFU) ---------------
        bool msk = (mA != 0.0f);
        P0 = msk ? S0 * G0 : P0 * H;
        P1 = msk ? S1 * G1 : P1 * H;
        redP = __reduce_max_sync(0xFFFFFFFFu, __float_as_int(fmaxf(P0, P1)));

        // ---- off-chain: log-domain shadow of alpha (output path) ---------
        float n0 = F0 + lg2(S0);
        float n1 = F1 + lg2(S1);
        A0 = fmaf(mA, n0 - A0, A0);
        A1 = fmaf(mA, n1 - A1, A1);

        // rotate shift + prefetch registers
        sC = sN;
        fA0 = fB0; fA1 = fB1; mA = mB;
        fB0 = fC0; fB1 = fC1; mB = mC;
        p ^= 1;
    }

    // back to natural log (from the exact log-domain shadow)
    out[b * TT + t0] = A0 * LN2;
    out[b * TT + t1] = A1 * LN2;
}

// ---------------------------------------------------------------------------
// launch
// ---------------------------------------------------------------------------
extern "C" void kernel_launch(void* const* d_in, const int* in_sizes, int n_in,
                              void* d_out, int out_size) {
    const float* feats = (const float*)d_in[0];  // [512, 1024, 64]
    const float* masks = (const float*)d_in[1];  // [512, 1024]
    const float* trans = (const float*)d_in[2];  // [64, 64]
    float* out = (float*)d_out;                  // [512, 64]

    crf_prep_kernel<<<TT, TT>>>(trans);
    crf_scan_kernel<<<CTAS, WARPS_PER_CTA * 32>>>(feats, masks, out);
}